// round 3
// baseline (speedup 1.0000x reference)
#include <cuda_runtime.h>

#define BB 16
#define TT 512
#define LL 128
#define NSTEP 129
#define ENCD 512
#define HD 1024
#define ED 512
#define VD 10000
#define AD 512

#define NBLK 148
#define NTHR 512
#define NWARP (NBLK * (NTHR / 32))

// ---- scratch (device globals; allocs are forbidden) ----
__device__ float g_encproj[(size_t)BB * TT * AD];
__device__ float g_h0[2][BB * HD];
__device__ float g_h1[2][BB * HD];
__device__ float g_c0[BB * HD];
__device__ float g_c1[BB * HD];
__device__ float g_ctx[BB * ENCD];
__device__ float g_dproj[BB * AD];
__device__ float g_aw[BB * TT];
__device__ float g_dcat[(size_t)NSTEP * BB * 1536];   // [t][b][dec|ctx]
__device__ float g_attnv[(size_t)NSTEP * BB * HD];
__device__ unsigned g_bar;
__device__ volatile unsigned g_gen;

__device__ __forceinline__ float sigf(float x) { return __fdividef(1.f, 1.f + __expf(-x)); }
__device__ __forceinline__ float tanhf_fast(float x) {
    float z = __expf(2.f * x);
    return 1.f - __fdividef(2.f, z + 1.f);
}

__device__ __forceinline__ void grid_sync(unsigned& mygen) {
    __syncthreads();
    if (threadIdx.x == 0) {
        unsigned tgt = mygen + 1u;
        __threadfence();
        if (atomicAdd(&g_bar, 1u) == NBLK - 1) {
            g_bar = 0u;
            __threadfence();
            g_gen = tgt;
        } else {
            while (g_gen < tgt) { }
            __threadfence();
        }
    }
    mygen += 1u;
    __syncthreads();
}

#define DOT4(S, X, W) \
    S = fmaf((X).x, (W).x, S); S = fmaf((X).y, (W).y, S); \
    S = fmaf((X).z, (W).z, S); S = fmaf((X).w, (W).w, S);

// 4-gate dot over a 1024-wide x given as two 512 halves (x0 -> cols 0..511, x1 -> 512..1023)
__device__ __forceinline__ void acc4(float& si, float& sf, float& sg, float& so,
                                     const float* __restrict__ x0, const float* __restrict__ x1,
                                     const float* __restrict__ W, int u, int lane) {
    const float* w0 = W + (size_t)u * 1024;
    const float* w1 = W + (size_t)(u + HD) * 1024;
    const float* w2 = W + (size_t)(u + 2 * HD) * 1024;
    const float* w3 = W + (size_t)(u + 3 * HD) * 1024;
    #pragma unroll
    for (int k = lane * 4; k < 512; k += 128) {
        float4 xa = *(const float4*)(x0 + k);
        float4 a = __ldcs((const float4*)(w0 + k));
        float4 b = __ldcs((const float4*)(w1 + k));
        float4 c = __ldcs((const float4*)(w2 + k));
        float4 d = __ldcs((const float4*)(w3 + k));
        DOT4(si, xa, a); DOT4(sf, xa, b); DOT4(sg, xa, c); DOT4(so, xa, d);
        float4 xb = *(const float4*)(x1 + k);
        a = __ldcs((const float4*)(w0 + 512 + k));
        b = __ldcs((const float4*)(w1 + 512 + k));
        c = __ldcs((const float4*)(w2 + 512 + k));
        d = __ldcs((const float4*)(w3 + 512 + k));
        DOT4(si, xb, a); DOT4(sf, xb, b); DOT4(sg, xb, c); DOT4(so, xb, d);
    }
}

__device__ __forceinline__ void wredux4(float& a, float& b, float& c, float& d) {
    #pragma unroll
    for (int off = 16; off > 0; off >>= 1) {
        a += __shfl_xor_sync(0xffffffffu, a, off);
        b += __shfl_xor_sync(0xffffffffu, b, off);
        c += __shfl_xor_sync(0xffffffffu, c, off);
        d += __shfl_xor_sync(0xffffffffu, d, off);
    }
}

__global__ void init_kernel() {
    int i = blockIdx.x * blockDim.x + threadIdx.x;
    if (i < BB * HD) { g_h0[0][i] = 0.f; g_c0[i] = 0.f; g_h1[0][i] = 0.f; g_c1[i] = 0.f; }
    if (i < BB * ENCD) g_ctx[i] = 0.f;
    if (i == 0) { g_bar = 0u; g_gen = 0u; }
}

__global__ __launch_bounds__(NTHR, 1) void dec_persistent(
    const float* __restrict__ enc_out, const int* __restrict__ enc_lens,
    const int* __restrict__ ys, const float* __restrict__ embed,
    const float* __restrict__ Wih0, const float* __restrict__ Whh0, const float* __restrict__ bi0,
    const float* __restrict__ Wih1, const float* __restrict__ Whh1, const float* __restrict__ bi1,
    const float* __restrict__ Wdec, const float* __restrict__ vatt)
{
    const int lane = threadIdx.x & 31;
    const int gw = blockIdx.x * (NTHR / 32) + (threadIdx.x >> 5);
    unsigned mygen = 0;

    for (int t = 0; t < NSTEP; ++t) {
        const int par = t & 1;
        const float* h0r = g_h0[par];
        float* h0w = g_h0[par ^ 1];
        const float* h1r = g_h1[par];
        float* h1w = g_h1[par ^ 1];

        // P1: LSTM0 — one warp per (b,u)
        for (int unit = gw; unit < BB * HD; unit += NWARP) {
            const int b = unit >> 10, u = unit & (HD - 1);
            const int tok = (t == 0) ? 1 : ys[b * LL + (t - 1)];
            float si = 0.f, sf = 0.f, sg = 0.f, so = 0.f;
            acc4(si, sf, sg, so, embed + (size_t)tok * ED, g_ctx + b * ENCD, Wih0, u, lane);
            acc4(si, sf, sg, so, h0r + b * HD, h0r + b * HD + 512, Whh0, u, lane);
            wredux4(si, sf, sg, so);
            if (lane == 0) {
                si += bi0[u]; sf += bi0[u + HD]; sg += bi0[u + 2 * HD]; so += bi0[u + 3 * HD];
                float c = sigf(sf) * g_c0[unit] + sigf(si) * tanhf_fast(sg);
                g_c0[unit] = c;
                h0w[unit] = sigf(so) * tanhf_fast(c);
            }
        }
        grid_sync(mygen);

        // P2: LSTM1 + dec = h1new + h0new
        for (int unit = gw; unit < BB * HD; unit += NWARP) {
            const int b = unit >> 10, u = unit & (HD - 1);
            const float* xa = h0w + b * HD;
            const float* xb = h1r + b * HD;
            float si = 0.f, sf = 0.f, sg = 0.f, so = 0.f;
            acc4(si, sf, sg, so, xa, xa + 512, Wih1, u, lane);
            acc4(si, sf, sg, so, xb, xb + 512, Whh1, u, lane);
            wredux4(si, sf, sg, so);
            if (lane == 0) {
                si += bi1[u]; sf += bi1[u + HD]; sg += bi1[u + 2 * HD]; so += bi1[u + 3 * HD];
                float c = sigf(sf) * g_c1[unit] + sigf(si) * tanhf_fast(sg);
                g_c1[unit] = c;
                float h1n = sigf(so) * tanhf_fast(c);
                h1w[unit] = h1n;
                g_dcat[((size_t)t * BB + b) * 1536 + u] = h1n + xa[u];
            }
        }
        grid_sync(mygen);

        // P3: dproj = dec @ W_dec  (warp -> (b, 32 cols of A))
        for (int job = gw; job < BB * (AD / 32); job += NWARP) {
            const int b = job >> 4;
            const int a0 = (job & 15) << 5;
            const float* dec = g_dcat + ((size_t)t * BB + b) * 1536;
            const float* w = Wdec + a0 + lane;
            float s0 = 0.f, s1 = 0.f, s2 = 0.f, s3 = 0.f;
            for (int k = 0; k < HD; k += 4) {
                s0 = fmaf(dec[k], w[(size_t)k * AD], s0);
                s1 = fmaf(dec[k + 1], w[(size_t)(k + 1) * AD], s1);
                s2 = fmaf(dec[k + 2], w[(size_t)(k + 2) * AD], s2);
                s3 = fmaf(dec[k + 3], w[(size_t)(k + 3) * AD], s3);
            }
            g_dproj[b * AD + a0 + lane] = (s0 + s1) + (s2 + s3);
        }
        grid_sync(mygen);

        // P4: e = v . tanh(encproj + dproj); store masked exp(e) (|e|<~9 so no max shift)
        for (int job = gw; job < BB * TT; job += NWARP) {
            const int b = job >> 9, tt = job & (TT - 1);
            const float4* p4 = (const float4*)(g_encproj + (size_t)(b * TT + tt) * AD);
            const float4* d4 = (const float4*)(g_dproj + b * AD);
            const float4* v4 = (const float4*)vatt;
            float s = 0.f;
            #pragma unroll
            for (int i = lane; i < AD / 4; i += 32) {
                float4 p = __ldcs(p4 + i); float4 d = d4[i]; float4 v = v4[i];
                s = fmaf(v.x, tanhf_fast(p.x + d.x), s);
                s = fmaf(v.y, tanhf_fast(p.y + d.y), s);
                s = fmaf(v.z, tanhf_fast(p.z + d.z), s);
                s = fmaf(v.w, tanhf_fast(p.w + d.w), s);
            }
            #pragma unroll
            for (int off = 16; off > 0; off >>= 1) s += __shfl_xor_sync(0xffffffffu, s, off);
            if (lane == 0) g_aw[b * TT + tt] = (tt < enc_lens[b]) ? __expf(s) : 0.f;
        }
        grid_sync(mygen);

        // P5: ctx = (sum w*enc)/(sum w); also write ctx half of dcat
        for (int job = gw; job < BB * (ENCD / 32); job += NWARP) {
            const int b = job >> 4;
            const int col = ((job & 15) << 5) + lane;
            const float* ao = g_aw + b * TT;
            const float* eo = enc_out + (size_t)b * TT * ENCD + col;
            float s0 = 0.f, s1 = 0.f, m0 = 0.f, m1 = 0.f;
            for (int tt = 0; tt < TT; tt += 2) {
                float w0 = ao[tt], w1 = ao[tt + 1];
                m0 += w0; m1 += w1;
                s0 = fmaf(w0, __ldcs(eo + (size_t)tt * ENCD), s0);
                s1 = fmaf(w1, __ldcs(eo + (size_t)(tt + 1) * ENCD), s1);
            }
            float cv = (s0 + s1) / (m0 + m1);
            g_ctx[b * ENCD + col] = cv;
            g_dcat[((size_t)t * BB + b) * 1536 + 1024 + col] = cv;
        }
        grid_sync(mygen);
    }
}

// ---- generic tiled fp32 GEMM: C = act(A[M,K] @ B[K,N] + bias) ----
// mode 0: plain; mode 1: tanh; mode 2: plain + row remap (m=t*16+b -> (b*129+t))
#define GBM 128
#define GBN 64
#define GBK 16

__global__ __launch_bounds__(256) void gemm_kernel(
    const float* __restrict__ Am, const float* __restrict__ Bm,
    const float* __restrict__ bias, float* __restrict__ Cm,
    int M, int N, int K, int mode)
{
    __shared__ float As[GBK][GBM + 4];
    __shared__ float Bs[GBK][GBN];
    const int tid = threadIdx.x;
    const int tx = tid & 15, ty = tid >> 4;
    const int n0 = blockIdx.x * GBN;
    const int m0 = blockIdx.y * GBM;
    float acc[8][4];
    #pragma unroll
    for (int r = 0; r < 8; r++)
        #pragma unroll
        for (int c = 0; c < 4; c++) acc[r][c] = 0.f;

    for (int k0 = 0; k0 < K; k0 += GBK) {
        #pragma unroll
        for (int i = tid; i < (GBM * GBK) / 4; i += 256) {
            int row = i >> 2, kq = (i & 3) << 2;
            float4 v = make_float4(0.f, 0.f, 0.f, 0.f);
            int gm = m0 + row;
            if (gm < M) v = *(const float4*)(Am + (size_t)gm * K + k0 + kq);
            As[kq][row] = v.x; As[kq + 1][row] = v.y; As[kq + 2][row] = v.z; As[kq + 3][row] = v.w;
        }
        {
            int row = tid >> 4, nq = (tid & 15) << 2;
            float4 v = make_float4(0.f, 0.f, 0.f, 0.f);
            if (n0 + nq < N) v = *(const float4*)(Bm + (size_t)(k0 + row) * N + n0 + nq);
            *(float4*)&Bs[row][nq] = v;
        }
        __syncthreads();
        #pragma unroll
        for (int k = 0; k < GBK; k++) {
            float4 bv = *(const float4*)&Bs[k][tx << 2];
            #pragma unroll
            for (int r = 0; r < 8; r++) {
                float a = As[k][(ty << 3) + r];
                acc[r][0] = fmaf(a, bv.x, acc[r][0]);
                acc[r][1] = fmaf(a, bv.y, acc[r][1]);
                acc[r][2] = fmaf(a, bv.z, acc[r][2]);
                acc[r][3] = fmaf(a, bv.w, acc[r][3]);
            }
        }
        __syncthreads();
    }
    #pragma unroll
    for (int r = 0; r < 8; r++) {
        int m = m0 + (ty << 3) + r;
        if (m >= M) continue;
        size_t base = (mode == 2)
            ? ((size_t)(m & 15) * NSTEP + (m >> 4)) * (size_t)N
            : (size_t)m * N;
        #pragma unroll
        for (int c = 0; c < 4; c++) {
            int n = n0 + (tx << 2) + c;
            if (n >= N) continue;
            float v = acc[r][c] + bias[n];
            if (mode == 1) v = tanhf_fast(v);
            Cm[base + n] = v;
        }
    }
}

extern "C" void kernel_launch(void* const* d_in, const int* in_sizes, int n_in,
                              void* d_out, int out_size)
{
    const float* enc_out  = (const float*)d_in[0];
    const int*   enc_lens = (const int*)d_in[1];
    const int*   ys       = (const int*)d_in[2];
    const float* embed    = (const float*)d_in[3];
    const float* Wih0     = (const float*)d_in[4];
    const float* Whh0     = (const float*)d_in[5];
    const float* b0       = (const float*)d_in[6];
    const float* Wih1     = (const float*)d_in[7];
    const float* Whh1     = (const float*)d_in[8];
    const float* b1       = (const float*)d_in[9];
    const float* W_enc    = (const float*)d_in[10];
    const float* b_att    = (const float*)d_in[11];
    const float* v_att    = (const float*)d_in[12];
    const float* W_dec    = (const float*)d_in[13];
    const float* W_bn     = (const float*)d_in[14];
    const float* b_bn     = (const float*)d_in[15];
    const float* W_out    = (const float*)d_in[16];
    const float* b_out    = (const float*)d_in[17];
    float* out = (float*)d_out;

    float *p_encproj, *p_dcat, *p_attnv;
    cudaGetSymbolAddress((void**)&p_encproj, g_encproj);
    cudaGetSymbolAddress((void**)&p_dcat, g_dcat);
    cudaGetSymbolAddress((void**)&p_attnv, g_attnv);

    init_kernel<<<(BB * HD + 255) / 256, 256>>>();

    // enc_proj = enc_out @ W_enc + b_att   [8192,512]x[512,512]
    {
        dim3 grid(AD / GBN, (BB * TT + GBM - 1) / GBM);
        gemm_kernel<<<grid, 256>>>(enc_out, W_enc, b_att, p_encproj, BB * TT, AD, ENCD, 0);
    }

    dec_persistent<<<NBLK, NTHR>>>(enc_out, enc_lens, ys, embed,
                                   Wih0, Whh0, b0, Wih1, Whh1, b1, W_dec, v_att);

    // attn_v = tanh(dcat @ W_bn + b_bn)    [2064,1536]x[1536,1024]
    {
        dim3 grid(HD / GBN, (NSTEP * BB + GBM - 1) / GBM);
        gemm_kernel<<<grid, 256>>>(p_dcat, W_bn, b_bn, p_attnv, NSTEP * BB, HD, 1536, 1);
    }
    // logits = attn_v @ W_out + b_out  (remapped to [B,129,V])
    {
        dim3 grid((VD + GBN - 1) / GBN, (NSTEP * BB + GBM - 1) / GBM);
        gemm_kernel<<<grid, 256>>>(p_attnv, W_out, b_out, out, NSTEP * BB, VD, HD, 2);
    }
    (void)in_sizes; (void)n_in; (void)out_size;
}

// round 4
// speedup vs baseline: 1.5186x; 1.5186x over previous
#include <cuda_runtime.h>

#define BB 16
#define TT 512
#define LL 128
#define NSTEP 129
#define ENCD 512
#define HD 1024
#define ED 512
#define VD 10000
#define AD 512

#define NBLK 148
#define NTHR 512
#define NWARP (NBLK * (NTHR / 32))

// ---- scratch (device globals; allocs are forbidden) ----
__device__ float g_encproj[(size_t)BB * TT * AD];
__device__ float g_h0[2][BB * HD];
__device__ float g_h1[2][BB * HD];
__device__ float g_c0[BB * HD];
__device__ float g_c1[BB * HD];
__device__ float g_ctx[BB * ENCD];
__device__ float g_dproj[BB * AD];
__device__ float g_aw[BB * TT];
__device__ float g_dcat[(size_t)NSTEP * BB * 1536];   // [t][b][dec|ctx]
__device__ float g_attnv[(size_t)NSTEP * BB * HD];
__device__ unsigned g_bar;
__device__ volatile unsigned g_gen;

__device__ __forceinline__ float sigf(float x) { return __fdividef(1.f, 1.f + __expf(-x)); }
__device__ __forceinline__ float tanhf_fast(float x) {
    float z = __expf(2.f * x);
    return 1.f - __fdividef(2.f, z + 1.f);
}

__device__ __forceinline__ void grid_sync(unsigned& mygen) {
    __syncthreads();
    if (threadIdx.x == 0) {
        unsigned tgt = mygen + 1u;
        __threadfence();
        if (atomicAdd(&g_bar, 1u) == NBLK - 1) {
            g_bar = 0u;
            __threadfence();
            g_gen = tgt;
        } else {
            while (g_gen < tgt) { }
            __threadfence();
        }
    }
    mygen += 1u;
    __syncthreads();
}

#define DOT4(S, X, W) \
    S = fmaf((X).x, (W).x, S); S = fmaf((X).y, (W).y, S); \
    S = fmaf((X).z, (W).z, S); S = fmaf((X).w, (W).w, S);

// Distributed butterfly: afterwards lane l holds total (over lanes) of acc[l].
#define RSTAGE(OFF, HALF) \
    { bool hi = (lane & OFF) != 0; \
      _Pragma("unroll") \
      for (int i = 0; i < HALF; ++i) { \
          float o0 = __shfl_xor_sync(0xffffffffu, acc[i], OFF); \
          float o1 = __shfl_xor_sync(0xffffffffu, acc[i + HALF], OFF); \
          acc[i] = hi ? (acc[i + HALF] + o1) : (acc[i] + o0); \
      } }

__global__ void init_kernel() {
    int i = blockIdx.x * blockDim.x + threadIdx.x;
    if (i < BB * HD) { g_h0[0][i] = 0.f; g_c0[i] = 0.f; g_h1[0][i] = 0.f; g_c1[i] = 0.f; }
    if (i < BB * ENCD) g_ctx[i] = 0.f;
    if (i == 0) { g_bar = 0u; g_gen = 0u; }
}

// One LSTM layer pass. Jobs: 2048 = 1024 units x 2 batch-groups of 8.
// LAYER 0: x_ih = [emb(tok) | ctx], x_hh = h0_prev. LAYER 1: x_ih = h0_new, x_hh = h1_prev.
template<int LAYER>
__device__ __forceinline__ void lstm_pass(
    int t, int gw, int lane,
    const int* __restrict__ ys, const float* __restrict__ embed,
    const float* __restrict__ Wih, const float* __restrict__ Whh, const float* __restrict__ bi,
    const float* __restrict__ hprev,   // x for hh-segment
    const float* __restrict__ h0new,   // LAYER1: x for ih-segment (also dec residual)
    float* __restrict__ cbuf, float* __restrict__ hout)
{
    for (int j = gw; j < 2048; j += NWARP) {
        const int u = j >> 1;
        const int b0 = (j & 1) << 3;
        int tok[8];
        if (LAYER == 0) {
            #pragma unroll
            for (int b = 0; b < 8; ++b)
                tok[b] = (t == 0) ? 1 : ys[(b0 + b) * LL + (t - 1)];
        }
        float acc[32];
        #pragma unroll
        for (int i = 0; i < 32; ++i) acc[i] = 0.f;

        // segment 0: W_ih
        #pragma unroll
        for (int c = 0; c < 8; ++c) {
            const int k0 = c * 128 + lane * 4;
            float4 xr[8];
            #pragma unroll
            for (int b = 0; b < 8; ++b) {
                const float* px;
                if (LAYER == 0)
                    px = (c < 4) ? (embed + (size_t)tok[b] * ED + k0)
                                 : (g_ctx + (b0 + b) * ENCD + (k0 - 512));
                else
                    px = h0new + (b0 + b) * HD + k0;
                xr[b] = *(const float4*)px;
            }
            #pragma unroll
            for (int g = 0; g < 4; ++g) {
                float4 w = __ldcs((const float4*)(Wih + (size_t)(u + g * HD) * 1024 + k0));
                #pragma unroll
                for (int b = 0; b < 8; ++b) { DOT4(acc[g * 8 + b], xr[b], w); }
            }
        }
        // segment 1: W_hh, x = hprev
        #pragma unroll
        for (int c = 0; c < 8; ++c) {
            const int k0 = c * 128 + lane * 4;
            float4 xr[8];
            #pragma unroll
            for (int b = 0; b < 8; ++b)
                xr[b] = *(const float4*)(hprev + (b0 + b) * HD + k0);
            #pragma unroll
            for (int g = 0; g < 4; ++g) {
                float4 w = __ldcs((const float4*)(Whh + (size_t)(u + g * HD) * 1024 + k0));
                #pragma unroll
                for (int b = 0; b < 8; ++b) { DOT4(acc[g * 8 + b], xr[b], w); }
            }
        }

        RSTAGE(16, 16) RSTAGE(8, 8) RSTAGE(4, 4) RSTAGE(2, 2) RSTAGE(1, 1)
        // lane l holds S[l], l = g*8 + b. Hand lanes 0..7 all four gates:
        float v = acc[0];
        float sf = __shfl_sync(0xffffffffu, v, (lane & 7) + 8);
        float sg = __shfl_sync(0xffffffffu, v, (lane & 7) + 16);
        float so = __shfl_sync(0xffffffffu, v, (lane & 7) + 24);
        if (lane < 8) {
            const int b = b0 + lane;
            const int idx = b * HD + u;
            float si_ = v + bi[u];
            float sf_ = sf + bi[u + HD];
            float sg_ = sg + bi[u + 2 * HD];
            float so_ = so + bi[u + 3 * HD];
            float c = sigf(sf_) * cbuf[idx] + sigf(si_) * tanhf_fast(sg_);
            cbuf[idx] = c;
            float h = sigf(so_) * tanhf_fast(c);
            hout[idx] = h;
            if (LAYER == 1)
                g_dcat[((size_t)t * BB + b) * 1536 + u] = h + h0new[idx];
        }
    }
}

__global__ __launch_bounds__(NTHR, 1) void dec_persistent(
    const float* __restrict__ enc_out, const int* __restrict__ enc_lens,
    const int* __restrict__ ys, const float* __restrict__ embed,
    const float* __restrict__ Wih0, const float* __restrict__ Whh0, const float* __restrict__ bi0,
    const float* __restrict__ Wih1, const float* __restrict__ Whh1, const float* __restrict__ bi1,
    const float* __restrict__ Wdec, const float* __restrict__ vatt)
{
    const int lane = threadIdx.x & 31;
    const int gw = blockIdx.x * (NTHR / 32) + (threadIdx.x >> 5);
    unsigned mygen = 0;

    for (int t = 0; t < NSTEP; ++t) {
        const int par = t & 1;
        const float* h0r = g_h0[par];
        float* h0w = g_h0[par ^ 1];
        const float* h1r = g_h1[par];
        float* h1w = g_h1[par ^ 1];

        // P1: LSTM layer 0
        lstm_pass<0>(t, gw, lane, ys, embed, Wih0, Whh0, bi0, h0r, h0w /*unused as x*/, g_c0, h0w);
        grid_sync(mygen);

        // P2: LSTM layer 1 (+ dec residual into dcat)
        lstm_pass<1>(t, gw, lane, ys, embed, Wih1, Whh1, bi1, h1r, h0w, g_c1, h1w);
        grid_sync(mygen);

        // P3: dproj = dec @ W_dec  (warp -> (b, 32 cols of A))
        for (int job = gw; job < BB * (AD / 32); job += NWARP) {
            const int b = job >> 4;
            const int a0 = (job & 15) << 5;
            const float* dec = g_dcat + ((size_t)t * BB + b) * 1536;
            const float* w = Wdec + a0 + lane;
            float s0 = 0.f, s1 = 0.f, s2 = 0.f, s3 = 0.f;
            for (int k = 0; k < HD; k += 4) {
                s0 = fmaf(dec[k], w[(size_t)k * AD], s0);
                s1 = fmaf(dec[k + 1], w[(size_t)(k + 1) * AD], s1);
                s2 = fmaf(dec[k + 2], w[(size_t)(k + 2) * AD], s2);
                s3 = fmaf(dec[k + 3], w[(size_t)(k + 3) * AD], s3);
            }
            g_dproj[b * AD + a0 + lane] = (s0 + s1) + (s2 + s3);
        }
        grid_sync(mygen);

        // P4: e = v . tanh(encproj + dproj); store masked exp(e) (|e| small, no max shift)
        for (int job = gw; job < BB * TT; job += NWARP) {
            const int b = job >> 9, tt = job & (TT - 1);
            const float4* p4 = (const float4*)(g_encproj + (size_t)(b * TT + tt) * AD);
            const float4* d4 = (const float4*)(g_dproj + b * AD);
            const float4* v4 = (const float4*)vatt;
            float s = 0.f;
            #pragma unroll
            for (int i = lane; i < AD / 4; i += 32) {
                float4 p = __ldcs(p4 + i); float4 d = d4[i]; float4 vv = v4[i];
                s = fmaf(vv.x, tanhf_fast(p.x + d.x), s);
                s = fmaf(vv.y, tanhf_fast(p.y + d.y), s);
                s = fmaf(vv.z, tanhf_fast(p.z + d.z), s);
                s = fmaf(vv.w, tanhf_fast(p.w + d.w), s);
            }
            #pragma unroll
            for (int off = 16; off > 0; off >>= 1) s += __shfl_xor_sync(0xffffffffu, s, off);
            if (lane == 0) g_aw[b * TT + tt] = (tt < enc_lens[b]) ? __expf(s) : 0.f;
        }
        grid_sync(mygen);

        // P5: ctx = (sum w*enc)/(sum w); also write ctx half of dcat
        for (int job = gw; job < BB * (ENCD / 32); job += NWARP) {
            const int b = job >> 4;
            const int col = ((job & 15) << 5) + lane;
            const float* ao = g_aw + b * TT;
            const float* eo = enc_out + (size_t)b * TT * ENCD + col;
            float s0 = 0.f, s1 = 0.f, m0 = 0.f, m1 = 0.f;
            for (int tt = 0; tt < TT; tt += 2) {
                float w0 = ao[tt], w1 = ao[tt + 1];
                m0 += w0; m1 += w1;
                s0 = fmaf(w0, __ldcs(eo + (size_t)tt * ENCD), s0);
                s1 = fmaf(w1, __ldcs(eo + (size_t)(tt + 1) * ENCD), s1);
            }
            float cv = (s0 + s1) / (m0 + m1);
            g_ctx[b * ENCD + col] = cv;
            g_dcat[((size_t)t * BB + b) * 1536 + 1024 + col] = cv;
        }
        grid_sync(mygen);
    }
}

// ---- generic tiled fp32 GEMM: C = act(A[M,K] @ B[K,N] + bias) ----
// mode 0: plain; mode 1: tanh; mode 2: plain + row remap (m=t*16+b -> (b*129+t))
#define GBM 128
#define GBN 64
#define GBK 16

__global__ __launch_bounds__(256) void gemm_kernel(
    const float* __restrict__ Am, const float* __restrict__ Bm,
    const float* __restrict__ bias, float* __restrict__ Cm,
    int M, int N, int K, int mode)
{
    __shared__ float As[GBK][GBM + 4];
    __shared__ float Bs[GBK][GBN];
    const int tid = threadIdx.x;
    const int tx = tid & 15, ty = tid >> 4;
    const int n0 = blockIdx.x * GBN;
    const int m0 = blockIdx.y * GBM;
    float acc[8][4];
    #pragma unroll
    for (int r = 0; r < 8; r++)
        #pragma unroll
        for (int c = 0; c < 4; c++) acc[r][c] = 0.f;

    for (int k0 = 0; k0 < K; k0 += GBK) {
        #pragma unroll
        for (int i = tid; i < (GBM * GBK) / 4; i += 256) {
            int row = i >> 2, kq = (i & 3) << 2;
            float4 v = make_float4(0.f, 0.f, 0.f, 0.f);
            int gm = m0 + row;
            if (gm < M) v = *(const float4*)(Am + (size_t)gm * K + k0 + kq);
            As[kq][row] = v.x; As[kq + 1][row] = v.y; As[kq + 2][row] = v.z; As[kq + 3][row] = v.w;
        }
        {
            int row = tid >> 4, nq = (tid & 15) << 2;
            float4 v = make_float4(0.f, 0.f, 0.f, 0.f);
            if (n0 + nq < N) v = *(const float4*)(Bm + (size_t)(k0 + row) * N + n0 + nq);
            *(float4*)&Bs[row][nq] = v;
        }
        __syncthreads();
        #pragma unroll
        for (int k = 0; k < GBK; k++) {
            float4 bv = *(const float4*)&Bs[k][tx << 2];
            #pragma unroll
            for (int r = 0; r < 8; r++) {
                float a = As[k][(ty << 3) + r];
                acc[r][0] = fmaf(a, bv.x, acc[r][0]);
                acc[r][1] = fmaf(a, bv.y, acc[r][1]);
                acc[r][2] = fmaf(a, bv.z, acc[r][2]);
                acc[r][3] = fmaf(a, bv.w, acc[r][3]);
            }
        }
        __syncthreads();
    }
    #pragma unroll
    for (int r = 0; r < 8; r++) {
        int m = m0 + (ty << 3) + r;
        if (m >= M) continue;
        size_t base = (mode == 2)
            ? ((size_t)(m & 15) * NSTEP + (m >> 4)) * (size_t)N
            : (size_t)m * N;
        #pragma unroll
        for (int c = 0; c < 4; c++) {
            int n = n0 + (tx << 2) + c;
            if (n >= N) continue;
            float v = acc[r][c] + bias[n];
            if (mode == 1) v = tanhf_fast(v);
            Cm[base + n] = v;
        }
    }
}

extern "C" void kernel_launch(void* const* d_in, const int* in_sizes, int n_in,
                              void* d_out, int out_size)
{
    const float* enc_out  = (const float*)d_in[0];
    const int*   enc_lens = (const int*)d_in[1];
    const int*   ys       = (const int*)d_in[2];
    const float* embed    = (const float*)d_in[3];
    const float* Wih0     = (const float*)d_in[4];
    const float* Whh0     = (const float*)d_in[5];
    const float* b0       = (const float*)d_in[6];
    const float* Wih1     = (const float*)d_in[7];
    const float* Whh1     = (const float*)d_in[8];
    const float* b1       = (const float*)d_in[9];
    const float* W_enc    = (const float*)d_in[10];
    const float* b_att    = (const float*)d_in[11];
    const float* v_att    = (const float*)d_in[12];
    const float* W_dec    = (const float*)d_in[13];
    const float* W_bn     = (const float*)d_in[14];
    const float* b_bn     = (const float*)d_in[15];
    const float* W_out    = (const float*)d_in[16];
    const float* b_out    = (const float*)d_in[17];
    float* out = (float*)d_out;

    float *p_encproj, *p_dcat, *p_attnv;
    cudaGetSymbolAddress((void**)&p_encproj, g_encproj);
    cudaGetSymbolAddress((void**)&p_dcat, g_dcat);
    cudaGetSymbolAddress((void**)&p_attnv, g_attnv);

    init_kernel<<<(BB * HD + 255) / 256, 256>>>();

    // enc_proj = enc_out @ W_enc + b_att   [8192,512]x[512,512]
    {
        dim3 grid(AD / GBN, (BB * TT + GBM - 1) / GBM);
        gemm_kernel<<<grid, 256>>>(enc_out, W_enc, b_att, p_encproj, BB * TT, AD, ENCD, 0);
    }

    dec_persistent<<<NBLK, NTHR>>>(enc_out, enc_lens, ys, embed,
                                   Wih0, Whh0, b0, Wih1, Whh1, b1, W_dec, v_att);

    // attn_v = tanh(dcat @ W_bn + b_bn)    [2064,1536]x[1536,1024]
    {
        dim3 grid(HD / GBN, (NSTEP * BB + GBM - 1) / GBM);
        gemm_kernel<<<grid, 256>>>(p_dcat, W_bn, b_bn, p_attnv, NSTEP * BB, HD, 1536, 1);
    }
    // logits = attn_v @ W_out + b_out  (remapped to [B,129,V])
    {
        dim3 grid((VD + GBN - 1) / GBN, (NSTEP * BB + GBM - 1) / GBM);
        gemm_kernel<<<grid, 256>>>(p_attnv, W_out, b_out, out, NSTEP * BB, VD, HD, 2);
    }
    (void)in_sizes; (void)n_in; (void)out_size;
}

// round 5
// speedup vs baseline: 2.3692x; 1.5602x over previous
#include <cuda_runtime.h>

#define BB 16
#define TT 512
#define LL 128
#define NSTEP 129
#define ENCD 512
#define HD 1024
#define ED 512
#define VD 10000
#define AD 512

#define NBLK 148
#define NTHR 512
#define NWARP (NBLK * (NTHR / 32))

// ---- scratch (device globals; allocs are forbidden) ----
__device__ float g_encproj[(size_t)BB * TT * AD];
__device__ float g_h0[2][BB * HD];
__device__ float g_h1[2][BB * HD];
__device__ float g_c0[BB * HD];
__device__ float g_c1[BB * HD];
__device__ float g_ctx[2][BB * ENCD];      // double-buffered: read par, accumulate par^1
__device__ float g_dproj[BB * AD];
__device__ float g_aw[BB * TT];
__device__ float g_awsum[BB];
__device__ float g_dcat[(size_t)NSTEP * BB * 1536];   // [t][b][dec|ctx]
__device__ float g_attnv[(size_t)NSTEP * BB * HD];
__device__ unsigned g_bar;
__device__ volatile unsigned g_gen;

__device__ __forceinline__ float sigf(float x) { return __fdividef(1.f, 1.f + __expf(-x)); }
__device__ __forceinline__ float tanhf_fast(float x) {
    float z = __expf(2.f * x);
    return 1.f - __fdividef(2.f, z + 1.f);
}

__device__ __forceinline__ void grid_sync(unsigned& mygen) {
    __syncthreads();
    if (threadIdx.x == 0) {
        unsigned tgt = mygen + 1u;
        __threadfence();
        if (atomicAdd(&g_bar, 1u) == NBLK - 1) {
            g_bar = 0u;
            __threadfence();
            g_gen = tgt;
        } else {
            while (g_gen < tgt) { __nanosleep(64); }
            __threadfence();
        }
    }
    mygen += 1u;
    __syncthreads();
}

#define DOT4(S, X, W) \
    S = fmaf((X).x, (W).x, S); S = fmaf((X).y, (W).y, S); \
    S = fmaf((X).z, (W).z, S); S = fmaf((X).w, (W).w, S);

// Distributed butterfly: afterwards lane l holds total (over lanes) of acc[l].
#define RSTAGE(OFF, HALF) \
    { bool hi = (lane & OFF) != 0; \
      _Pragma("unroll") \
      for (int i = 0; i < HALF; ++i) { \
          float o0 = __shfl_xor_sync(0xffffffffu, acc[i], OFF); \
          float o1 = __shfl_xor_sync(0xffffffffu, acc[i + HALF], OFF); \
          acc[i] = hi ? (acc[i + HALF] + o1) : (acc[i] + o0); \
      } }

__global__ void init_kernel() {
    int i = blockIdx.x * blockDim.x + threadIdx.x;
    if (i < BB * HD) { g_h0[0][i] = 0.f; g_c0[i] = 0.f; g_h1[0][i] = 0.f; g_c1[i] = 0.f; }
    if (i < BB * ENCD) g_ctx[0][i] = 0.f;
    if (i == 0) { g_bar = 0u; g_gen = 0u; }
}

__global__ void marker_kernel() {}   // ncu alignment: makes dec_persistent the captured launch

// One LSTM layer pass. Jobs: 2048 = 1024 units x 2 batch-groups of 8.
template<int LAYER>
__device__ __forceinline__ void lstm_pass(
    int t, int gw, int lane,
    const int* __restrict__ ys, const float* __restrict__ embed,
    const float* __restrict__ Wih, const float* __restrict__ Whh, const float* __restrict__ bi,
    const float* __restrict__ ctx,     // LAYER0 ih upper half
    const float* __restrict__ hprev,   // x for hh-segment
    const float* __restrict__ h0new,   // LAYER1: x for ih-segment (also dec residual)
    float* __restrict__ cbuf, float* __restrict__ hout)
{
    for (int j = gw; j < 2048; j += NWARP) {
        const int u = j >> 1;
        const int b0 = (j & 1) << 3;
        int tok[8];
        if (LAYER == 0) {
            #pragma unroll
            for (int b = 0; b < 8; ++b)
                tok[b] = (t == 0) ? 1 : ys[(b0 + b) * LL + (t - 1)];
        }
        float acc[32];
        #pragma unroll
        for (int i = 0; i < 32; ++i) acc[i] = 0.f;

        #pragma unroll
        for (int c = 0; c < 8; ++c) {
            const int k0 = c * 128 + lane * 4;
            float4 xr[8];
            #pragma unroll
            for (int b = 0; b < 8; ++b) {
                const float* px;
                if (LAYER == 0)
                    px = (c < 4) ? (embed + (size_t)tok[b] * ED + k0)
                                 : (ctx + (b0 + b) * ENCD + (k0 - 512));
                else
                    px = h0new + (b0 + b) * HD + k0;
                xr[b] = *(const float4*)px;
            }
            #pragma unroll
            for (int g = 0; g < 4; ++g) {
                float4 w = __ldcs((const float4*)(Wih + (size_t)(u + g * HD) * 1024 + k0));
                #pragma unroll
                for (int b = 0; b < 8; ++b) { DOT4(acc[g * 8 + b], xr[b], w); }
            }
        }
        #pragma unroll
        for (int c = 0; c < 8; ++c) {
            const int k0 = c * 128 + lane * 4;
            float4 xr[8];
            #pragma unroll
            for (int b = 0; b < 8; ++b)
                xr[b] = *(const float4*)(hprev + (b0 + b) * HD + k0);
            #pragma unroll
            for (int g = 0; g < 4; ++g) {
                float4 w = __ldcs((const float4*)(Whh + (size_t)(u + g * HD) * 1024 + k0));
                #pragma unroll
                for (int b = 0; b < 8; ++b) { DOT4(acc[g * 8 + b], xr[b], w); }
            }
        }

        RSTAGE(16, 16) RSTAGE(8, 8) RSTAGE(4, 4) RSTAGE(2, 2) RSTAGE(1, 1)
        float v = acc[0];
        float sf = __shfl_sync(0xffffffffu, v, (lane & 7) + 8);
        float sg = __shfl_sync(0xffffffffu, v, (lane & 7) + 16);
        float so = __shfl_sync(0xffffffffu, v, (lane & 7) + 24);
        if (lane < 8) {
            const int b = b0 + lane;
            const int idx = b * HD + u;
            float si_ = v + bi[u];
            float sf_ = sf + bi[u + HD];
            float sg_ = sg + bi[u + 2 * HD];
            float so_ = so + bi[u + 3 * HD];
            float c = sigf(sf_) * cbuf[idx] + sigf(si_) * tanhf_fast(sg_);
            cbuf[idx] = c;
            float h = sigf(so_) * tanhf_fast(c);
            hout[idx] = h;
            if (LAYER == 1)
                g_dcat[((size_t)t * BB + b) * 1536 + u] = h + h0new[idx];
        }
    }
}

__global__ __launch_bounds__(NTHR, 1) void dec_persistent(
    const float* __restrict__ enc_out, const int* __restrict__ enc_lens,
    const int* __restrict__ ys, const float* __restrict__ embed,
    const float* __restrict__ Wih0, const float* __restrict__ Whh0, const float* __restrict__ bi0,
    const float* __restrict__ Wih1, const float* __restrict__ Whh1, const float* __restrict__ bi1,
    const float* __restrict__ Wdec, const float* __restrict__ vatt)
{
    const int lane = threadIdx.x & 31;
    const int gw = blockIdx.x * (NTHR / 32) + (threadIdx.x >> 5);
    const int gt = blockIdx.x * NTHR + threadIdx.x;
    unsigned mygen = 0;

    for (int t = 0; t < NSTEP; ++t) {
        const int par = t & 1;
        const float* h0r = g_h0[par];
        float* h0w = g_h0[par ^ 1];
        const float* h1r = g_h1[par];
        float* h1w = g_h1[par ^ 1];
        const float* ctxr = g_ctx[par];
        float* ctxw = g_ctx[par ^ 1];

        // P1: LSTM layer 0; tail: zero dproj
        lstm_pass<0>(t, gw, lane, ys, embed, Wih0, Whh0, bi0, ctxr, h0r, h0w, g_c0, h0w);
        if (gt < BB * AD) g_dproj[gt] = 0.f;
        grid_sync(mygen);

        // P2: LSTM layer 1 (+ dec residual); tail: zero ctx(par^1), dcat ctx-half, awsum
        lstm_pass<1>(t, gw, lane, ys, embed, Wih1, Whh1, bi1, ctxr, h1r, h0w, g_c1, h1w);
        if (gt < BB * ENCD) {
            ctxw[gt] = 0.f;
            g_dcat[((size_t)t * BB + (gt >> 9)) * 1536 + 1024 + (gt & 511)] = 0.f;
        }
        if (gt < BB) g_awsum[gt] = 0.f;
        grid_sync(mygen);

        // P3: dproj partials: jobs = b(16) x colgrp(16 of 32) x ksplit(8 of 128)
        for (int job = gw; job < 2048; job += NWARP) {
            const int b = job >> 7;
            const int cg = (job >> 3) & 15;
            const int ks = job & 7;
            const int a0 = cg << 5;
            const float* dec = g_dcat + ((size_t)t * BB + b) * 1536 + ks * 128;
            const float* w = Wdec + (size_t)(ks * 128) * AD + a0 + lane;
            float s0 = 0.f, s1 = 0.f, s2 = 0.f, s3 = 0.f;
            #pragma unroll 8
            for (int k = 0; k < 128; k += 4) {
                s0 = fmaf(dec[k], w[(size_t)k * AD], s0);
                s1 = fmaf(dec[k + 1], w[(size_t)(k + 1) * AD], s1);
                s2 = fmaf(dec[k + 2], w[(size_t)(k + 2) * AD], s2);
                s3 = fmaf(dec[k + 3], w[(size_t)(k + 3) * AD], s3);
            }
            atomicAdd(&g_dproj[b * AD + a0 + lane], (s0 + s1) + (s2 + s3));
        }
        grid_sync(mygen);

        // P4: e = v . tanh(encproj + dproj); aw = masked exp(e); awsum += aw
        for (int job = gw; job < BB * TT; job += NWARP) {
            const int b = job >> 9, tt = job & (TT - 1);
            const float4* p4 = (const float4*)(g_encproj + (size_t)(b * TT + tt) * AD);
            const float4* d4 = (const float4*)(g_dproj + b * AD);
            const float4* v4 = (const float4*)vatt;
            float s = 0.f;
            #pragma unroll
            for (int i = lane; i < AD / 4; i += 32) {
                float4 p = __ldcs(p4 + i); float4 d = d4[i]; float4 vv = v4[i];
                s = fmaf(vv.x, tanhf_fast(p.x + d.x), s);
                s = fmaf(vv.y, tanhf_fast(p.y + d.y), s);
                s = fmaf(vv.z, tanhf_fast(p.z + d.z), s);
                s = fmaf(vv.w, tanhf_fast(p.w + d.w), s);
            }
            #pragma unroll
            for (int off = 16; off > 0; off >>= 1) s += __shfl_xor_sync(0xffffffffu, s, off);
            if (lane == 0) {
                float w = (tt < enc_lens[b]) ? __expf(s) : 0.f;
                g_aw[b * TT + tt] = w;
                if (w != 0.f) atomicAdd(&g_awsum[b], w);
            }
        }
        grid_sync(mygen);

        // P5: ctx partials (pre-scaled by 1/awsum): jobs = b(16) x colgrp(16) x ttsplit(8 of 64)
        for (int job = gw; job < 2048; job += NWARP) {
            const int b = job >> 7;
            const int cg = (job >> 3) & 15;
            const int ts = job & 7;
            const int col = (cg << 5) + lane;
            const float inv = __fdividef(1.f, g_awsum[b]);
            const float* ao = g_aw + b * TT + ts * 64;
            const float* eo = enc_out + (size_t)b * TT * ENCD + (size_t)(ts * 64) * ENCD + col;
            float s0 = 0.f, s1 = 0.f;
            #pragma unroll 8
            for (int tt = 0; tt < 64; tt += 2) {
                s0 = fmaf(ao[tt], __ldcs(eo + (size_t)tt * ENCD), s0);
                s1 = fmaf(ao[tt + 1], __ldcs(eo + (size_t)(tt + 1) * ENCD), s1);
            }
            float cv = (s0 + s1) * inv;
            atomicAdd(&ctxw[b * ENCD + col], cv);
            atomicAdd(&g_dcat[((size_t)t * BB + b) * 1536 + 1024 + col], cv);
        }
        grid_sync(mygen);
    }
}

// ---- generic tiled fp32 GEMM: C = act(A[M,K] @ B[K,N] + bias) ----
// mode 0: plain; mode 1: tanh; mode 2: plain + row remap (m=t*16+b -> (b*129+t))
#define GBM 128
#define GBN 64
#define GBK 16

__global__ __launch_bounds__(256) void gemm_kernel(
    const float* __restrict__ Am, const float* __restrict__ Bm,
    const float* __restrict__ bias, float* __restrict__ Cm,
    int M, int N, int K, int mode)
{
    __shared__ float As[GBK][GBM + 4];
    __shared__ float Bs[GBK][GBN];
    const int tid = threadIdx.x;
    const int tx = tid & 15, ty = tid >> 4;
    const int n0 = blockIdx.x * GBN;
    const int m0 = blockIdx.y * GBM;
    float acc[8][4];
    #pragma unroll
    for (int r = 0; r < 8; r++)
        #pragma unroll
        for (int c = 0; c < 4; c++) acc[r][c] = 0.f;

    for (int k0 = 0; k0 < K; k0 += GBK) {
        #pragma unroll
        for (int i = tid; i < (GBM * GBK) / 4; i += 256) {
            int row = i >> 2, kq = (i & 3) << 2;
            float4 v = make_float4(0.f, 0.f, 0.f, 0.f);
            int gm = m0 + row;
            if (gm < M) v = *(const float4*)(Am + (size_t)gm * K + k0 + kq);
            As[kq][row] = v.x; As[kq + 1][row] = v.y; As[kq + 2][row] = v.z; As[kq + 3][row] = v.w;
        }
        {
            int row = tid >> 4, nq = (tid & 15) << 2;
            float4 v = make_float4(0.f, 0.f, 0.f, 0.f);
            if (n0 + nq < N) v = *(const float4*)(Bm + (size_t)(k0 + row) * N + n0 + nq);
            *(float4*)&Bs[row][nq] = v;
        }
        __syncthreads();
        #pragma unroll
        for (int k = 0; k < GBK; k++) {
            float4 bv = *(const float4*)&Bs[k][tx << 2];
            #pragma unroll
            for (int r = 0; r < 8; r++) {
                float a = As[k][(ty << 3) + r];
                acc[r][0] = fmaf(a, bv.x, acc[r][0]);
                acc[r][1] = fmaf(a, bv.y, acc[r][1]);
                acc[r][2] = fmaf(a, bv.z, acc[r][2]);
                acc[r][3] = fmaf(a, bv.w, acc[r][3]);
            }
        }
        __syncthreads();
    }
    #pragma unroll
    for (int r = 0; r < 8; r++) {
        int m = m0 + (ty << 3) + r;
        if (m >= M) continue;
        size_t base = (mode == 2)
            ? ((size_t)(m & 15) * NSTEP + (m >> 4)) * (size_t)N
            : (size_t)m * N;
        #pragma unroll
        for (int c = 0; c < 4; c++) {
            int n = n0 + (tx << 2) + c;
            if (n >= N) continue;
            float v = acc[r][c] + bias[n];
            if (mode == 1) v = tanhf_fast(v);
            Cm[base + n] = v;
        }
    }
}

extern "C" void kernel_launch(void* const* d_in, const int* in_sizes, int n_in,
                              void* d_out, int out_size)
{
    const float* enc_out  = (const float*)d_in[0];
    const int*   enc_lens = (const int*)d_in[1];
    const int*   ys       = (const int*)d_in[2];
    const float* embed    = (const float*)d_in[3];
    const float* Wih0     = (const float*)d_in[4];
    const float* Whh0     = (const float*)d_in[5];
    const float* b0       = (const float*)d_in[6];
    const float* Wih1     = (const float*)d_in[7];
    const float* Whh1     = (const float*)d_in[8];
    const float* b1       = (const float*)d_in[9];
    const float* W_enc    = (const float*)d_in[10];
    const float* b_att    = (const float*)d_in[11];
    const float* v_att    = (const float*)d_in[12];
    const float* W_dec    = (const float*)d_in[13];
    const float* W_bn     = (const float*)d_in[14];
    const float* b_bn     = (const float*)d_in[15];
    const float* W_out    = (const float*)d_in[16];
    const float* b_out    = (const float*)d_in[17];
    float* out = (float*)d_out;

    float *p_encproj, *p_dcat, *p_attnv;
    cudaGetSymbolAddress((void**)&p_encproj, g_encproj);
    cudaGetSymbolAddress((void**)&p_dcat, g_dcat);
    cudaGetSymbolAddress((void**)&p_attnv, g_attnv);

    init_kernel<<<(BB * HD + 255) / 256, 256>>>();

    // enc_proj = enc_out @ W_enc + b_att   [8192,512]x[512,512]
    {
        dim3 grid(AD / GBN, (BB * TT + GBM - 1) / GBM);
        gemm_kernel<<<grid, 256>>>(enc_out, W_enc, b_att, p_encproj, BB * TT, AD, ENCD, 0);
    }

    marker_kernel<<<1, 1>>>();   // shifts capture slot onto dec_persistent

    dec_persistent<<<NBLK, NTHR>>>(enc_out, enc_lens, ys, embed,
                                   Wih0, Whh0, b0, Wih1, Whh1, b1, W_dec, v_att);

    // attn_v = tanh(dcat @ W_bn + b_bn)    [2064,1536]x[1536,1024]
    {
        dim3 grid(HD / GBN, (NSTEP * BB + GBM - 1) / GBM);
        gemm_kernel<<<grid, 256>>>(p_dcat, W_bn, b_bn, p_attnv, NSTEP * BB, HD, 1536, 1);
    }
    // logits = attn_v @ W_out + b_out  (remapped to [B,129,V])
    {
        dim3 grid((VD + GBN - 1) / GBN, (NSTEP * BB + GBM - 1) / GBM);
        gemm_kernel<<<grid, 256>>>(p_attnv, W_out, b_out, out, NSTEP * BB, VD, HD, 2);
    }
    (void)in_sizes; (void)n_in; (void)out_size;
}